// round 2
// baseline (speedup 1.0000x reference)
#include <cuda_runtime.h>
#include <cstdint>

#define BATCH 64
#define SEQ   1024
#define DIN   256
#define UNITS 512

// ================= xW GEMM: C[65536,512] = X[65536,256] @ W[256,512] ==========
#define GM_TM 128
#define GM_TN 128
#define GM_TK 16

// ---- global state for the scan kernel (static device allocs are allowed) ----
__device__ float g_h[2][BATCH][UNITS];
__device__ unsigned g_count[2];
__device__ volatile unsigned g_release[2];

__global__ void __launch_bounds__(256) xw_gemm_kernel(const float* __restrict__ X,
                                                      const float* __restrict__ W,
                                                      float* __restrict__ C) {
    // reset scan-kernel barrier state every launch (graph-replay safe)
    if (blockIdx.x == 0 && blockIdx.y == 0 && threadIdx.x == 0) {
        g_count[0] = 0u; g_count[1] = 0u;
        g_release[0] = 0u; g_release[1] = 0u;
    }

    __shared__ float As[GM_TK][GM_TM + 4];   // stored transposed: As[k][m]
    __shared__ float Bs[GM_TK][GM_TN + 4];

    const int tid = threadIdx.x;            // 256 threads
    const int bm = blockIdx.y * GM_TM;
    const int bn = blockIdx.x * GM_TN;
    const int tx = tid & 15;                 // 16 thread cols
    const int ty = tid >> 4;                 // 16 thread rows

    float acc[8][8];
#pragma unroll
    for (int i = 0; i < 8; i++)
#pragma unroll
        for (int j = 0; j < 8; j++) acc[i][j] = 0.0f;

    const int arow = tid >> 2;               // 0..63
    const int acol = (tid & 3) * 4;          // 0,4,8,12
    const int brow = tid >> 5;               // 0..7
    const int bcol = (tid & 31) * 4;         // 0..124

    for (int k0 = 0; k0 < DIN; k0 += GM_TK) {
#pragma unroll
        for (int p = 0; p < 2; p++) {
            float4 v = *(const float4*)&X[(size_t)(bm + arow + p * 64) * DIN + k0 + acol];
            As[acol + 0][arow + p * 64] = v.x;
            As[acol + 1][arow + p * 64] = v.y;
            As[acol + 2][arow + p * 64] = v.z;
            As[acol + 3][arow + p * 64] = v.w;
        }
#pragma unroll
        for (int p = 0; p < 2; p++) {
            *(float4*)&Bs[brow + p * 8][bcol] =
                *(const float4*)&W[(size_t)(k0 + brow + p * 8) * UNITS + bn + bcol];
        }
        __syncthreads();

#pragma unroll
        for (int kk = 0; kk < GM_TK; kk++) {
            float a[8], bb[8];
            *(float4*)&a[0]  = *(const float4*)&As[kk][ty * 8];
            *(float4*)&a[4]  = *(const float4*)&As[kk][ty * 8 + 4];
            *(float4*)&bb[0] = *(const float4*)&Bs[kk][tx * 8];
            *(float4*)&bb[4] = *(const float4*)&Bs[kk][tx * 8 + 4];
#pragma unroll
            for (int i = 0; i < 8; i++)
#pragma unroll
                for (int j = 0; j < 8; j++)
                    acc[i][j] = fmaf(a[i], bb[j], acc[i][j]);
        }
        __syncthreads();
    }

#pragma unroll
    for (int i = 0; i < 8; i++) {
        size_t row = (size_t)(bm + ty * 8 + i) * UNITS + bn + tx * 8;
        float4 v0 = make_float4(acc[i][0], acc[i][1], acc[i][2], acc[i][3]);
        float4 v1 = make_float4(acc[i][4], acc[i][5], acc[i][6], acc[i][7]);
        *(float4*)&C[row]     = v0;
        *(float4*)&C[row + 4] = v1;
    }
}

// ================= LTC scan: persistent, 128 CTAs, 2 batch-group barriers =====
#define BT 32                 // batches per group
#define UT 8                  // units per CTA
#define HPAD 516              // padded row stride (floats) -> conflict-free LDS
#define SCAN_CTAS 128
#define SCAN_SMEM ((UT + BT) * HPAD * 4)

__device__ __forceinline__ void group_barrier(int grp, unsigned gen) {
    // callers already did: per-thread __threadfence(); __syncthreads();
    if (threadIdx.x == 0) {
        unsigned prev = atomicAdd(&g_count[grp], 1u);
        if (prev == 64u * (gen + 1u) - 1u) {
            __threadfence();
            g_release[grp] = gen + 1u;
        } else {
            while (g_release[grp] <= gen) { __nanosleep(64); }
        }
        __threadfence();
    }
    __syncthreads();
}

__global__ void __launch_bounds__(256) ltc_scan_kernel(const float* __restrict__ U,
                                                       const float* __restrict__ bias,
                                                       const float* __restrict__ tau,
                                                       float* out) {
    extern __shared__ float sm[];
    float* Us = sm;                 // [UT][HPAD]  persistent U columns (transposed)
    float* hs = sm + UT * HPAD;     // [BT][HPAD]  per-step staged h

    const int tid = threadIdx.x;
    const int cta = blockIdx.x;         // 0..127
    const int grp = cta >> 6;           // 0..1 : batch group
    const int usl = cta & 63;           // u-slice within group
    const int b0  = grp * BT;
    const int u0  = usl * UT;
    const int ul  = tid & (UT - 1);     // 0..7
    const int bl  = tid >> 3;           // 0..31
    const int b   = b0 + bl;
    const int u   = u0 + ul;

    // load this CTA's 8 U columns, transposed: Us[uc][k] = U[k][u0+uc]  (once)
    for (int idx = tid; idx < UT * UNITS; idx += 256) {
        int uc = idx >> 9;          // /512
        int k  = idx & 511;
        Us[uc * HPAD + k] = U[(size_t)k * UNITS + u0 + uc];
    }

    const float invt = 1.0f / tau[u];
    const float aa   = 1.0f - invt;
    const float bi   = bias[u];

    g_h[0][b][u] = 0.0f;            // h0 = 0 (each (b,u) written exactly once)
    __threadfence();
    __syncthreads();
    group_barrier(grp, 0u);

    int cur = 0;
    float* orow = out + (size_t)b * SEQ * UNITS + u;

    for (int t = 0; t < SEQ; t++) {
        // stage h[b0..b0+31][0..511] (L2-coherent loads; L1 would be stale)
#pragma unroll
        for (int p = 0; p < 16; p++) {
            int idx = tid + p * 256;          // 0..4095 float4s
            int r = idx >> 7;                 // 0..31
            int c = (idx & 127) << 2;         // 0..508
            float4 v = __ldcg((const float4*)&g_h[cur][b0 + r][c]);
            *(float4*)&hs[r * HPAD + c] = v;
        }
        __syncthreads();

        const float* hrow = hs + bl * HPAD;
        const float* ucol = Us + ul * HPAD;
        float a0 = 0.f, a1 = 0.f, a2 = 0.f, a3 = 0.f;
#pragma unroll 16
        for (int k = 0; k < UNITS; k += 4) {
            float4 hv = *(const float4*)(hrow + k);
            float4 uv = *(const float4*)(ucol + k);
            a0 = fmaf(hv.x, uv.x, a0);
            a1 = fmaf(hv.y, uv.y, a1);
            a2 = fmaf(hv.z, uv.z, a2);
            a3 = fmaf(hv.w, uv.w, a3);
        }
        float acc = (a0 + a1) + (a2 + a3);

        float xw = orow[(size_t)t * UNITS];
        float hn = fmaf(aa, hrow[u], invt * (acc + xw + bi));

        g_h[cur ^ 1][b][u]    = hn;
        orow[(size_t)t * UNITS] = hn;

        __threadfence();
        __syncthreads();
        group_barrier(grp, (unsigned)(t + 1));
        cur ^= 1;
    }
}

// =============================== launch ======================================
extern "C" void kernel_launch(void* const* d_in, const int* in_sizes, int n_in,
                              void* d_out, int out_size) {
    const float* x    = (const float*)d_in[0];   // [64,1024,256]
    const float* W    = (const float*)d_in[1];   // [256,512]
    const float* U    = (const float*)d_in[2];   // [512,512]
    const float* bias = (const float*)d_in[3];   // [512]
    const float* tau  = (const float*)d_in[4];   // [512]
    float* out = (float*)d_out;                  // [64,1024,512]

    // 1) xW -> out  (also resets scan barrier state)
    dim3 ggrid(UNITS / GM_TN, (BATCH * SEQ) / GM_TM);   // (4, 512)
    xw_gemm_kernel<<<ggrid, 256>>>(x, W, out);

    // 2) scan in-place over out
    cudaFuncSetAttribute(ltc_scan_kernel,
                         cudaFuncAttributeMaxDynamicSharedMemorySize, SCAN_SMEM);
    ltc_scan_kernel<<<SCAN_CTAS, 256, SCAN_SMEM>>>(U, bias, tau, out);
}

// round 3
// speedup vs baseline: 1.8379x; 1.8379x over previous
#include <cuda_runtime.h>
#include <cstdint>

#define BATCH 64
#define SEQ   1024
#define DIN   256
#define UNITS 512

// ================= xW GEMM: C[65536,512] = X[65536,256] @ W[256,512] ==========
#define GM_TM 128
#define GM_TN 128
#define GM_TK 16

// ---- global state for the scan kernel ----
__device__ float g_h[2][BATCH][UNITS];
__device__ unsigned g_cnt[16];
__device__ volatile unsigned g_rel[16];

__global__ void __launch_bounds__(256) xw_gemm_kernel(const float* __restrict__ X,
                                                      const float* __restrict__ W,
                                                      float* __restrict__ C) {
    // reset scan-kernel barrier state every launch (graph-replay safe)
    if (blockIdx.x == 0 && blockIdx.y == 0 && threadIdx.x < 16) {
        g_cnt[threadIdx.x] = 0u;
        g_rel[threadIdx.x] = 0u;
    }

    __shared__ float As[GM_TK][GM_TM + 4];   // stored transposed: As[k][m]
    __shared__ float Bs[GM_TK][GM_TN + 4];

    const int tid = threadIdx.x;            // 256 threads
    const int bm = blockIdx.y * GM_TM;
    const int bn = blockIdx.x * GM_TN;
    const int tx = tid & 15;                 // 16 thread cols
    const int ty = tid >> 4;                 // 16 thread rows

    float acc[8][8];
#pragma unroll
    for (int i = 0; i < 8; i++)
#pragma unroll
        for (int j = 0; j < 8; j++) acc[i][j] = 0.0f;

    const int arow = tid >> 2;               // 0..63
    const int acol = (tid & 3) * 4;          // 0,4,8,12
    const int brow = tid >> 5;               // 0..7
    const int bcol = (tid & 31) * 4;         // 0..124

    for (int k0 = 0; k0 < DIN; k0 += GM_TK) {
#pragma unroll
        for (int p = 0; p < 2; p++) {
            float4 v = *(const float4*)&X[(size_t)(bm + arow + p * 64) * DIN + k0 + acol];
            As[acol + 0][arow + p * 64] = v.x;
            As[acol + 1][arow + p * 64] = v.y;
            As[acol + 2][arow + p * 64] = v.z;
            As[acol + 3][arow + p * 64] = v.w;
        }
#pragma unroll
        for (int p = 0; p < 2; p++) {
            *(float4*)&Bs[brow + p * 8][bcol] =
                *(const float4*)&W[(size_t)(k0 + brow + p * 8) * UNITS + bn + bcol];
        }
        __syncthreads();

#pragma unroll
        for (int kk = 0; kk < GM_TK; kk++) {
            float a[8], bb[8];
            *(float4*)&a[0]  = *(const float4*)&As[kk][ty * 8];
            *(float4*)&a[4]  = *(const float4*)&As[kk][ty * 8 + 4];
            *(float4*)&bb[0] = *(const float4*)&Bs[kk][tx * 8];
            *(float4*)&bb[4] = *(const float4*)&Bs[kk][tx * 8 + 4];
#pragma unroll
            for (int i = 0; i < 8; i++)
#pragma unroll
                for (int j = 0; j < 8; j++)
                    acc[i][j] = fmaf(a[i], bb[j], acc[i][j]);
        }
        __syncthreads();
    }

#pragma unroll
    for (int i = 0; i < 8; i++) {
        size_t row = (size_t)(bm + ty * 8 + i) * UNITS + bn + tx * 8;
        float4 v0 = make_float4(acc[i][0], acc[i][1], acc[i][2], acc[i][3]);
        float4 v1 = make_float4(acc[i][4], acc[i][5], acc[i][6], acc[i][7]);
        *(float4*)&C[row]     = v0;
        *(float4*)&C[row + 4] = v1;
    }
}

// ================= LTC scan =================================================
// 128 CTAs = 16 groups x 8 slices.
// Group g owns batches [4g, 4g+4); slice s owns units [64s, 64s+64).
// Warp w owns k-range [64w, 64w+64); lane l owns u-pair {64s+2l, 64s+2l+1}.
// U slice lives in REGISTERS (64k x 2u = 128 floats/thread, persistent).
#define SCAN_CTAS 128

__device__ __forceinline__ void group_barrier(int grp, unsigned gen) {
    if (threadIdx.x == 0) {
        unsigned prev = atomicAdd(&g_cnt[grp], 1u);
        if (prev == 8u * (gen + 1u) - 1u) {
            g_rel[grp] = gen + 1u;          // release
        } else {
            while (g_rel[grp] <= gen) { __nanosleep(32); }
        }
        __threadfence();                    // acquire
    }
    __syncthreads();
}

__global__ void __launch_bounds__(256, 1) ltc_scan_kernel(const float* __restrict__ U,
                                                          const float* __restrict__ bias,
                                                          const float* __restrict__ tau,
                                                          float* out) {
    __shared__ float hs[4][UNITS];          // staged h for this group's 4 batches
    __shared__ float ps[8][4][68];          // k-split partials [warp][b][u_local]

    const int tid = threadIdx.x;
    const int w   = tid >> 5;               // warp 0..7 -> k-range
    const int l   = tid & 31;               // lane -> u pair
    const int cta = blockIdx.x;
    const int g   = cta >> 3;               // group 0..15
    const int s   = cta & 7;                // unit slice 0..7
    const int b0  = g * 4;
    const int u0  = s * 64 + l * 2;

    // ---- load U slice into registers (once) ----
    float Ur[64][2];
#pragma unroll
    for (int k = 0; k < 64; k++) {
        float2 v = *(const float2*)&U[(size_t)(w * 64 + k) * UNITS + u0];
        Ur[k][0] = v.x;
        Ur[k][1] = v.y;
    }

    // ---- epilogue mapping: thread -> (batch eb, unit eu) of this CTA's block ----
    const int eb = tid >> 6;                // 0..3
    const int eul = tid & 63;               // 0..63
    const int eu  = s * 64 + eul;           // global unit index
    const float invt = 1.0f / tau[eu];
    const float aa   = 1.0f - invt;
    const float bi   = bias[eu];
    float* orow = out + (size_t)(b0 + eb) * SEQ * UNITS + eu;

    // ---- h0 = 0 ----
    g_h[0][b0 + eb][eu] = 0.0f;
    __threadfence();
    __syncthreads();
    group_barrier(g, 0u);

    for (int t = 0; t < SEQ; t++) {
        // xW for this thread's output element (independent of h -> hides under compute)
        float xw = __ldcg(orow + (size_t)t * UNITS);

        // ---- stage h for this group's 4 batches (2048 floats, L2-coherent) ----
        {
            const float4* src = (const float4*)&g_h[t & 1][b0][0];   // 512 float4
            float4 v0 = __ldcg(src + tid);
            float4 v1 = __ldcg(src + tid + 256);
            ((float4*)hs)[tid]       = v0;
            ((float4*)hs)[tid + 256] = v1;
        }
        __syncthreads();

        // ---- compute partial (h @ U) over this warp's k-range ----
        float acc[4][2] = {{0.f,0.f},{0.f,0.f},{0.f,0.f},{0.f,0.f}};
#pragma unroll
        for (int j = 0; j < 16; j++) {
            float h0a[4], h1a[4], h2a[4], h3a[4];
            *(float4*)h0a = *(const float4*)&hs[0][w * 64 + j * 4];  // warp-uniform LDS
            *(float4*)h1a = *(const float4*)&hs[1][w * 64 + j * 4];
            *(float4*)h2a = *(const float4*)&hs[2][w * 64 + j * 4];
            *(float4*)h3a = *(const float4*)&hs[3][w * 64 + j * 4];
#pragma unroll
            for (int kk = 0; kk < 4; kk++) {
                const float uv0 = Ur[j * 4 + kk][0];
                const float uv1 = Ur[j * 4 + kk][1];
                acc[0][0] = fmaf(h0a[kk], uv0, acc[0][0]);
                acc[0][1] = fmaf(h0a[kk], uv1, acc[0][1]);
                acc[1][0] = fmaf(h1a[kk], uv0, acc[1][0]);
                acc[1][1] = fmaf(h1a[kk], uv1, acc[1][1]);
                acc[2][0] = fmaf(h2a[kk], uv0, acc[2][0]);
                acc[2][1] = fmaf(h2a[kk], uv1, acc[2][1]);
                acc[3][0] = fmaf(h3a[kk], uv0, acc[3][0]);
                acc[3][1] = fmaf(h3a[kk], uv1, acc[3][1]);
            }
        }

        // ---- write k-split partials ----
#pragma unroll
        for (int b = 0; b < 4; b++) {
            ps[w][b][l * 2]     = acc[b][0];
            ps[w][b][l * 2 + 1] = acc[b][1];
        }
        __syncthreads();

        // ---- reduce across 8 warps; epilogue ----
        float r = 0.0f;
#pragma unroll
        for (int w2 = 0; w2 < 8; w2++) r += ps[w2][eb][eul];

        float hold = hs[eb][eu];
        float hn = fmaf(aa, hold, invt * (r + xw + bi));

        orow[(size_t)t * UNITS] = hn;
        g_h[(t & 1) ^ 1][b0 + eb][eu] = hn;

        __threadfence();
        group_barrier(g, (unsigned)(t + 1));
    }
}

// =============================== launch ======================================
extern "C" void kernel_launch(void* const* d_in, const int* in_sizes, int n_in,
                              void* d_out, int out_size) {
    const float* x    = (const float*)d_in[0];   // [64,1024,256]
    const float* W    = (const float*)d_in[1];   // [256,512]
    const float* U    = (const float*)d_in[2];   // [512,512]
    const float* bias = (const float*)d_in[3];   // [512]
    const float* tau  = (const float*)d_in[4];   // [512]
    float* out = (float*)d_out;                  // [64,1024,512]

    // 1) xW -> out  (also resets scan barrier state)
    dim3 ggrid(UNITS / GM_TN, (BATCH * SEQ) / GM_TM);   // (4, 512)
    xw_gemm_kernel<<<ggrid, 256>>>(x, W, out);

    // 2) scan in-place over out
    ltc_scan_kernel<<<SCAN_CTAS, 256>>>(U, bias, tau, out);
}

// round 4
// speedup vs baseline: 2.1792x; 1.1857x over previous
#include <cuda_runtime.h>
#include <cstdint>

#define BATCH 64
#define SEQ   1024
#define DIN   256
#define UNITS 512

// ================= xW GEMM: C[65536,512] = X[65536,256] @ W[256,512] ==========
#define GM_TM 128
#define GM_TN 128
#define GM_TK 16

__global__ void __launch_bounds__(256) xw_gemm_kernel(const float* __restrict__ X,
                                                      const float* __restrict__ W,
                                                      float* __restrict__ C) {
    __shared__ float As[GM_TK][GM_TM + 4];   // stored transposed: As[k][m]
    __shared__ float Bs[GM_TK][GM_TN + 4];

    const int tid = threadIdx.x;            // 256 threads
    const int bm = blockIdx.y * GM_TM;
    const int bn = blockIdx.x * GM_TN;
    const int tx = tid & 15;                 // 16 thread cols
    const int ty = tid >> 4;                 // 16 thread rows

    float acc[8][8];
#pragma unroll
    for (int i = 0; i < 8; i++)
#pragma unroll
        for (int j = 0; j < 8; j++) acc[i][j] = 0.0f;

    const int arow = tid >> 2;               // 0..63
    const int acol = (tid & 3) * 4;          // 0,4,8,12
    const int brow = tid >> 5;               // 0..7
    const int bcol = (tid & 31) * 4;         // 0..124

    for (int k0 = 0; k0 < DIN; k0 += GM_TK) {
#pragma unroll
        for (int p = 0; p < 2; p++) {
            float4 v = *(const float4*)&X[(size_t)(bm + arow + p * 64) * DIN + k0 + acol];
            As[acol + 0][arow + p * 64] = v.x;
            As[acol + 1][arow + p * 64] = v.y;
            As[acol + 2][arow + p * 64] = v.z;
            As[acol + 3][arow + p * 64] = v.w;
        }
#pragma unroll
        for (int p = 0; p < 2; p++) {
            *(float4*)&Bs[brow + p * 8][bcol] =
                *(const float4*)&W[(size_t)(k0 + brow + p * 8) * UNITS + bn + bcol];
        }
        __syncthreads();

#pragma unroll
        for (int kk = 0; kk < GM_TK; kk++) {
            float a[8], bb[8];
            *(float4*)&a[0]  = *(const float4*)&As[kk][ty * 8];
            *(float4*)&a[4]  = *(const float4*)&As[kk][ty * 8 + 4];
            *(float4*)&bb[0] = *(const float4*)&Bs[kk][tx * 8];
            *(float4*)&bb[4] = *(const float4*)&Bs[kk][tx * 8 + 4];
#pragma unroll
            for (int i = 0; i < 8; i++)
#pragma unroll
                for (int j = 0; j < 8; j++)
                    acc[i][j] = fmaf(a[i], bb[j], acc[i][j]);
        }
        __syncthreads();
    }

#pragma unroll
    for (int i = 0; i < 8; i++) {
        size_t row = (size_t)(bm + ty * 8 + i) * UNITS + bn + tx * 8;
        float4 v0 = make_float4(acc[i][0], acc[i][1], acc[i][2], acc[i][3]);
        float4 v1 = make_float4(acc[i][4], acc[i][5], acc[i][6], acc[i][7]);
        *(float4*)&C[row]     = v0;
        *(float4*)&C[row + 4] = v1;
    }
}

// ================= LTC scan: 16 clusters of 8 CTAs, DSMEM h exchange =========
// Cluster c owns batches [4c, 4c+4); rank s owns units [64s, 64s+64).
// Within a CTA: warp w owns k-range [64w, 64w+64); lane l owns u-pair.
// U slice lives in registers. h lives in double-buffered smem, replicated in
// every cluster CTA; producers push new h to all 8 ranks via st.shared::cluster.
#define CLUSTER_SZ 8
#define SCAN_CTAS 128

__device__ __forceinline__ void cluster_sync_() {
    asm volatile("barrier.cluster.arrive.aligned;" ::: "memory");
    asm volatile("barrier.cluster.wait.aligned;"   ::: "memory");
}

__device__ __forceinline__ void dsmem_store(uint32_t local_addr, int rank, float v) {
    uint32_t ra;
    asm volatile("mapa.shared::cluster.u32 %0, %1, %2;" : "=r"(ra) : "r"(local_addr), "r"(rank));
    asm volatile("st.shared::cluster.f32 [%0], %1;" :: "r"(ra), "f"(v) : "memory");
}

__global__ void __launch_bounds__(256, 1) __cluster_dims__(CLUSTER_SZ, 1, 1)
ltc_scan_kernel(const float* __restrict__ U,
                const float* __restrict__ bias,
                const float* __restrict__ tau,
                float* out) {
    __shared__ float hs[2][4][UNITS];       // double-buffered h, all 4 batches x 512 units
    __shared__ float ps[8][4][68];          // k-split partials [warp][b][u_local]

    const int tid = threadIdx.x;
    const int w   = tid >> 5;               // warp 0..7 -> k-range
    const int l   = tid & 31;               // lane -> u pair
    const int cta = blockIdx.x;
    const int s   = cta & 7;                // cluster rank = unit slice
    const int u0  = s * 64 + l * 2;
    const int b0  = (cta >> 3) * 4;         // cluster id * 4 batches

    // ---- load U slice into registers (once) ----
    float Ur0[64], Ur1[64];
#pragma unroll
    for (int k = 0; k < 64; k++) {
        float2 v = *(const float2*)&U[(size_t)(w * 64 + k) * UNITS + u0];
        Ur0[k] = v.x;
        Ur1[k] = v.y;
    }

    // ---- epilogue mapping: thread -> (batch eb, unit eu) ----
    const int eb  = tid >> 6;               // 0..3
    const int eul = tid & 63;               // 0..63
    const int eu  = s * 64 + eul;           // global unit index
    const float invt = 1.0f / tau[eu];
    const float aa   = 1.0f - invt;
    const float bi   = bias[eu];
    float* orow = out + (size_t)(b0 + eb) * SEQ * UNITS + eu;

    // ---- h0 = 0 in local buffer 0 ----
    for (int i = tid; i < 4 * UNITS; i += 256) ((float*)hs[0])[i] = 0.0f;

    // remote-store addresses for this thread's output element in both buffers
    const uint32_t a0 = (uint32_t)__cvta_generic_to_shared(&hs[0][eb][eu]);
    const uint32_t a1 = (uint32_t)__cvta_generic_to_shared(&hs[1][eb][eu]);

    float xw = __ldg(orow);                 // prefetch xW for t=0

    __syncthreads();
    cluster_sync_();

    for (int t = 0; t < SEQ; t++) {
        const int cur = t & 1;

        // ---- partial (h @ U) over this warp's k-range ----
        float acc00 = 0.f, acc01 = 0.f, acc10 = 0.f, acc11 = 0.f;
        float acc20 = 0.f, acc21 = 0.f, acc30 = 0.f, acc31 = 0.f;
#pragma unroll
        for (int j = 0; j < 16; j++) {
            float h0a[4], h1a[4], h2a[4], h3a[4];
            *(float4*)h0a = *(const float4*)&hs[cur][0][w * 64 + j * 4];  // warp-uniform LDS
            *(float4*)h1a = *(const float4*)&hs[cur][1][w * 64 + j * 4];
            *(float4*)h2a = *(const float4*)&hs[cur][2][w * 64 + j * 4];
            *(float4*)h3a = *(const float4*)&hs[cur][3][w * 64 + j * 4];
#pragma unroll
            for (int kk = 0; kk < 4; kk++) {
                const float uv0 = Ur0[j * 4 + kk];
                const float uv1 = Ur1[j * 4 + kk];
                acc00 = fmaf(h0a[kk], uv0, acc00);
                acc01 = fmaf(h0a[kk], uv1, acc01);
                acc10 = fmaf(h1a[kk], uv0, acc10);
                acc11 = fmaf(h1a[kk], uv1, acc11);
                acc20 = fmaf(h2a[kk], uv0, acc20);
                acc21 = fmaf(h2a[kk], uv1, acc21);
                acc30 = fmaf(h3a[kk], uv0, acc30);
                acc31 = fmaf(h3a[kk], uv1, acc31);
            }
        }

        // ---- write k-split partials ----
        *(float2*)&ps[w][0][l * 2] = make_float2(acc00, acc01);
        *(float2*)&ps[w][1][l * 2] = make_float2(acc10, acc11);
        *(float2*)&ps[w][2][l * 2] = make_float2(acc20, acc21);
        *(float2*)&ps[w][3][l * 2] = make_float2(acc30, acc31);
        __syncthreads();

        // ---- reduce across 8 warps; epilogue ----
        float r = 0.0f;
#pragma unroll
        for (int w2 = 0; w2 < 8; w2++) r += ps[w2][eb][eul];

        const float hold = hs[cur][eb][eu];
        const float hn = fmaf(aa, hold, invt * (r + xw + bi));

        // prefetch next xw (independent of h)
        if (t + 1 < SEQ) xw = __ldg(orow + (size_t)(t + 1) * UNITS);

        orow[(size_t)t * UNITS] = hn;

        // ---- push h_{t+1} into all 8 cluster CTAs' other buffer ----
        const uint32_t dst = cur ? a0 : a1;
#pragma unroll
        for (int rk = 0; rk < CLUSTER_SZ; rk++) dsmem_store(dst, rk, hn);

        // one cluster barrier per step: orders remote stores before next reads
        cluster_sync_();
    }
}

// =============================== launch ======================================
extern "C" void kernel_launch(void* const* d_in, const int* in_sizes, int n_in,
                              void* d_out, int out_size) {
    const float* x    = (const float*)d_in[0];   // [64,1024,256]
    const float* W    = (const float*)d_in[1];   // [256,512]
    const float* U    = (const float*)d_in[2];   // [512,512]
    const float* bias = (const float*)d_in[3];   // [512]
    const float* tau  = (const float*)d_in[4];   // [512]
    float* out = (float*)d_out;                  // [64,1024,512]

    // 1) xW -> out
    dim3 ggrid(UNITS / GM_TN, (BATCH * SEQ) / GM_TM);   // (4, 512)
    xw_gemm_kernel<<<ggrid, 256>>>(x, W, out);

    // 2) scan in-place over out (cluster dims are a compile-time attribute)
    ltc_scan_kernel<<<SCAN_CTAS, 256>>>(U, bias, tau, out);
}

// round 5
// speedup vs baseline: 2.8236x; 1.2957x over previous
#include <cuda_runtime.h>
#include <cstdint>

#define BATCH 64
#define SEQ   1024
#define DIN   256
#define UNITS 512

// ================= xW GEMM: C[65536,512] = X[65536,256] @ W[256,512] ==========
#define GM_TM 128
#define GM_TN 128
#define GM_TK 16

__global__ void __launch_bounds__(256) xw_gemm_kernel(const float* __restrict__ X,
                                                      const float* __restrict__ W,
                                                      float* __restrict__ C) {
    __shared__ float As[GM_TK][GM_TM + 4];   // stored transposed: As[k][m]
    __shared__ float Bs[GM_TK][GM_TN + 4];

    const int tid = threadIdx.x;            // 256 threads
    const int bm = blockIdx.y * GM_TM;
    const int bn = blockIdx.x * GM_TN;
    const int tx = tid & 15;                 // 16 thread cols
    const int ty = tid >> 4;                 // 16 thread rows

    float acc[8][8];
#pragma unroll
    for (int i = 0; i < 8; i++)
#pragma unroll
        for (int j = 0; j < 8; j++) acc[i][j] = 0.0f;

    const int arow = tid >> 2;               // 0..63
    const int acol = (tid & 3) * 4;          // 0,4,8,12
    const int brow = tid >> 5;               // 0..7
    const int bcol = (tid & 31) * 4;         // 0..124

    for (int k0 = 0; k0 < DIN; k0 += GM_TK) {
#pragma unroll
        for (int p = 0; p < 2; p++) {
            float4 v = *(const float4*)&X[(size_t)(bm + arow + p * 64) * DIN + k0 + acol];
            As[acol + 0][arow + p * 64] = v.x;
            As[acol + 1][arow + p * 64] = v.y;
            As[acol + 2][arow + p * 64] = v.z;
            As[acol + 3][arow + p * 64] = v.w;
        }
#pragma unroll
        for (int p = 0; p < 2; p++) {
            *(float4*)&Bs[brow + p * 8][bcol] =
                *(const float4*)&W[(size_t)(k0 + brow + p * 8) * UNITS + bn + bcol];
        }
        __syncthreads();

#pragma unroll
        for (int kk = 0; kk < GM_TK; kk++) {
            float a[8], bb[8];
            *(float4*)&a[0]  = *(const float4*)&As[kk][ty * 8];
            *(float4*)&a[4]  = *(const float4*)&As[kk][ty * 8 + 4];
            *(float4*)&bb[0] = *(const float4*)&Bs[kk][tx * 8];
            *(float4*)&bb[4] = *(const float4*)&Bs[kk][tx * 8 + 4];
#pragma unroll
            for (int i = 0; i < 8; i++)
#pragma unroll
                for (int j = 0; j < 8; j++)
                    acc[i][j] = fmaf(a[i], bb[j], acc[i][j]);
        }
        __syncthreads();
    }

#pragma unroll
    for (int i = 0; i < 8; i++) {
        size_t row = (size_t)(bm + ty * 8 + i) * UNITS + bn + tx * 8;
        float4 v0 = make_float4(acc[i][0], acc[i][1], acc[i][2], acc[i][3]);
        float4 v1 = make_float4(acc[i][4], acc[i][5], acc[i][6], acc[i][7]);
        *(float4*)&C[row]     = v0;
        *(float4*)&C[row + 4] = v1;
    }
}

// ================= LTC scan: clusters of 8, bulk DSMEM + mbarrier ============
// Cluster c owns batches [4c,4c+4). Rank s owns units [64s,64s+64).
// hs layout [buf][slice][batch][u_local]: each rank's produced 1KB is contiguous.
// Exchange: 7x cp.async.bulk (1KB) to peer ranks, complete_tx on peer mbar.
// Compute: packed fma.rn.f32x2 over (k,k+1) pairs; U in packed registers.
#define CLUSTER_SZ 8
#define SCAN_CTAS 128
#define SLICE_BYTES 1024                     // 4 batches * 64 units * 4B
#define EXPECT_BYTES (7 * SLICE_BYTES)

__device__ __forceinline__ void fma2(unsigned long long& d, unsigned long long a,
                                     unsigned long long b) {
    asm("fma.rn.f32x2 %0, %1, %2, %0;" : "+l"(d) : "l"(a), "l"(b));
}
__device__ __forceinline__ unsigned long long pack2(float x, float y) {
    unsigned long long r;
    asm("mov.b64 %0, {%1, %2};" : "=l"(r) : "f"(x), "f"(y));
    return r;
}
__device__ __forceinline__ float sum2(unsigned long long p) {
    float lo, hi;
    asm("mov.b64 {%0, %1}, %2;" : "=f"(lo), "=f"(hi) : "l"(p));
    return lo + hi;
}
__device__ __forceinline__ void cluster_sync_() {
    asm volatile("barrier.cluster.arrive.aligned;" ::: "memory");
    asm volatile("barrier.cluster.wait.aligned;"   ::: "memory");
}
__device__ __forceinline__ uint32_t mapa_u32(uint32_t addr, int rank) {
    uint32_t r;
    asm("mapa.shared::cluster.u32 %0, %1, %2;" : "=r"(r) : "r"(addr), "r"(rank));
    return r;
}
__device__ __forceinline__ void mbar_init(uint32_t mbar, uint32_t count) {
    asm volatile("mbarrier.init.shared.b64 [%0], %1;" :: "r"(mbar), "r"(count) : "memory");
}
__device__ __forceinline__ void mbar_expect_tx(uint32_t mbar, uint32_t bytes) {
    asm volatile("mbarrier.arrive.expect_tx.shared.b64 _, [%0], %1;"
                 :: "r"(mbar), "r"(bytes) : "memory");
}
__device__ __forceinline__ void mbar_wait(uint32_t mbar, uint32_t parity) {
    asm volatile(
        "{\n\t"
        ".reg .pred P1;\n\t"
        "WAIT_LOOP_%=:\n\t"
        "mbarrier.try_wait.parity.acquire.cta.shared::cta.b64 P1, [%0], %1, 0x989680;\n\t"
        "@P1 bra.uni WAIT_DONE_%=;\n\t"
        "bra.uni WAIT_LOOP_%=;\n\t"
        "WAIT_DONE_%=:\n\t"
        "}"
        :: "r"(mbar), "r"(parity) : "memory");
}
__device__ __forceinline__ void bulk_s2s(uint32_t dst_cluster, uint32_t src_cta,
                                         uint32_t bytes, uint32_t mbar_cluster) {
    asm volatile(
        "cp.async.bulk.shared::cluster.shared::cta.mbarrier::complete_tx::bytes "
        "[%0], [%1], %2, [%3];"
        :: "r"(dst_cluster), "r"(src_cta), "r"(bytes), "r"(mbar_cluster) : "memory");
}
__device__ __forceinline__ void fence_async_() {
    asm volatile("fence.proxy.async.shared::cta;" ::: "memory");
}

__global__ void __launch_bounds__(256, 1) __cluster_dims__(CLUSTER_SZ, 1, 1)
ltc_scan_kernel(const float* __restrict__ U,
                const float* __restrict__ bias,
                const float* __restrict__ tau,
                float* out) {
    __shared__ __align__(128) float hs[2][8][4][64];   // [buf][slice][batch][u_local]
    __shared__ float ps[8][4][68];                     // k-split partials
    __shared__ __align__(8) unsigned long long mbar[2];

    const int tid = threadIdx.x;
    const int w   = tid >> 5;               // warp -> k-slice (reads hs[.][w][.][.])
    const int l   = tid & 31;
    const int cta = blockIdx.x;
    const int s   = cta & 7;                // cluster rank = unit slice
    const int b0  = (cta >> 3) * 4;
    const int u0  = s * 64 + 2 * l;

    // ---- U slice in packed registers: Urp0/1[p] = {U[k][u],U[k+1][u]}, k=w*64+2p
    unsigned long long Urp0[32], Urp1[32];
#pragma unroll
    for (int p = 0; p < 32; p++) {
        const int k = w * 64 + 2 * p;
        float2 va = *(const float2*)&U[(size_t)k * UNITS + u0];
        float2 vb = *(const float2*)&U[(size_t)(k + 1) * UNITS + u0];
        Urp0[p] = pack2(va.x, vb.x);
        Urp1[p] = pack2(va.y, vb.y);
    }

    // ---- epilogue mapping ----
    const int eb  = tid >> 6;               // 0..3
    const int eul = tid & 63;               // 0..63
    const int eu  = s * 64 + eul;
    const float invt = 1.0f / tau[eu];
    const float aa   = 1.0f - invt;
    const float bi   = bias[eu];
    float* orow = out + (size_t)(b0 + eb) * SEQ * UNITS + eu;

    // ---- zero h0 buffer (full local copy) ----
    for (int i = tid; i < 8 * 4 * 64; i += 256) ((float*)hs[0])[i] = 0.0f;

    const uint32_t mbar_base  = (uint32_t)__cvta_generic_to_shared(&mbar[0]);
    const uint32_t slice_base0 = (uint32_t)__cvta_generic_to_shared(&hs[0][s][0][0]);
    const uint32_t slice_base1 = (uint32_t)__cvta_generic_to_shared(&hs[1][s][0][0]);

    if (tid == 0) {
        mbar_init(mbar_base, 1);
        mbar_init(mbar_base + 8, 1);
        mbar_expect_tx(mbar_base, EXPECT_BYTES);      // arms buffer0 (first used step 2)
        mbar_expect_tx(mbar_base + 8, EXPECT_BYTES);  // arms buffer1 (first used step 1)
    }
    __syncthreads();
    cluster_sync_();                         // mbars + h0 visible cluster-wide

    float xw = __ldg(orow);                  // prefetch xW for t=0
    int ph[2] = {0, 0};

    for (int t = 0; t < SEQ; t++) {
        const int cur = t & 1;
        const int nb  = cur ^ 1;

        if (t > 0) {
            mbar_wait(mbar_base + cur * 8, (uint32_t)ph[cur]);
            ph[cur] ^= 1;
            if (tid == 0) mbar_expect_tx(mbar_base + cur * 8, EXPECT_BYTES);  // re-arm for t+2
        }

        // ---- packed partial (h @ U) over this warp's k-slice ----
        unsigned long long a00 = 0ull, a01 = 0ull, a10 = 0ull, a11 = 0ull;
        unsigned long long a20 = 0ull, a21 = 0ull, a30 = 0ull, a31 = 0ull;
#pragma unroll
        for (int j = 0; j < 16; j++) {
            ulonglong2 h0 = *(const ulonglong2*)&hs[cur][w][0][j * 4];  // warp-uniform LDS
            ulonglong2 h1 = *(const ulonglong2*)&hs[cur][w][1][j * 4];
            ulonglong2 h2 = *(const ulonglong2*)&hs[cur][w][2][j * 4];
            ulonglong2 h3 = *(const ulonglong2*)&hs[cur][w][3][j * 4];
            fma2(a00, h0.x, Urp0[2 * j]);  fma2(a00, h0.y, Urp0[2 * j + 1]);
            fma2(a01, h0.x, Urp1[2 * j]);  fma2(a01, h0.y, Urp1[2 * j + 1]);
            fma2(a10, h1.x, Urp0[2 * j]);  fma2(a10, h1.y, Urp0[2 * j + 1]);
            fma2(a11, h1.x, Urp1[2 * j]);  fma2(a11, h1.y, Urp1[2 * j + 1]);
            fma2(a20, h2.x, Urp0[2 * j]);  fma2(a20, h2.y, Urp0[2 * j + 1]);
            fma2(a21, h2.x, Urp1[2 * j]);  fma2(a21, h2.y, Urp1[2 * j + 1]);
            fma2(a30, h3.x, Urp0[2 * j]);  fma2(a30, h3.y, Urp0[2 * j + 1]);
            fma2(a31, h3.x, Urp1[2 * j]);  fma2(a31, h3.y, Urp1[2 * j + 1]);
        }

        *(float2*)&ps[w][0][2 * l] = make_float2(sum2(a00), sum2(a01));
        *(float2*)&ps[w][1][2 * l] = make_float2(sum2(a10), sum2(a11));
        *(float2*)&ps[w][2][2 * l] = make_float2(sum2(a20), sum2(a21));
        *(float2*)&ps[w][3][2 * l] = make_float2(sum2(a30), sum2(a31));
        __syncthreads();

        // ---- reduce across 8 warps; epilogue ----
        float r = 0.0f;
#pragma unroll
        for (int w2 = 0; w2 < 8; w2++) r += ps[w2][eb][eul];

        const float hold = hs[cur][s][eb][eul];
        const float hn = fmaf(aa, hold, invt * (r + xw + bi));

        if (t + 1 < SEQ) xw = __ldg(orow + (size_t)(t + 1) * UNITS);
        orow[(size_t)t * UNITS] = hn;

        if (t + 1 < SEQ) {
            hs[nb][s][eb][eul] = hn;         // own slice stays local
            __syncthreads();                 // slice complete
            if (tid < 8 && tid != s) {       // push 1KB slice to 7 peers
                fence_async_();
                const uint32_t src = nb ? slice_base1 : slice_base0;
                const uint32_t dst = mapa_u32(src, tid);
                const uint32_t mb  = mapa_u32(mbar_base + nb * 8, tid);
                bulk_s2s(dst, src, SLICE_BYTES, mb);
            }
        }
    }

    cluster_sync_();                         // no CTA exits with peers' DMAs pending
}

// =============================== launch ======================================
extern "C" void kernel_launch(void* const* d_in, const int* in_sizes, int n_in,
                              void* d_out, int out_size) {
    const float* x    = (const float*)d_in[0];   // [64,1024,256]
    const float* W    = (const float*)d_in[1];   // [256,512]
    const float* U    = (const float*)d_in[2];   // [512,512]
    const float* bias = (const float*)d_in[3];   // [512]
    const float* tau  = (const float*)d_in[4];   // [512]
    float* out = (float*)d_out;                  // [64,1024,512]

    dim3 ggrid(UNITS / GM_TN, (BATCH * SEQ) / GM_TM);   // (4, 512)
    xw_gemm_kernel<<<ggrid, 256>>>(x, W, out);

    ltc_scan_kernel<<<SCAN_CTAS, 256>>>(U, bias, tau, out);
}